// round 3
// baseline (speedup 1.0000x reference)
#include <cuda_runtime.h>
#include <cstdint>

#define N_NODES   100000
#define N_EDGES   1600000
#define HID       128
#define NUM_G     64

// ---------------- scratch (static device globals; no allocation) ----------------
__device__ float g_bufA[(size_t)N_NODES * HID];
__device__ float g_bufB[(size_t)N_NODES * HID];
__device__ float g_agg [(size_t)N_NODES * HID];
__device__ float g_wt  [6 * HID * HID];        // transposed weights, k-major
__device__ float g_pool[NUM_G * HID];

// ---------------- zero ----------------
__global__ void zero_kernel(float* __restrict__ p, int n4) {
    int i = blockIdx.x * blockDim.x + threadIdx.x;
    if (i < n4) reinterpret_cast<float4*>(p)[i] = make_float4(0.f, 0.f, 0.f, 0.f);
}

// ---------------- transpose 6 weight matrices [128x128] -> k-major ----------------
__global__ void transpose6_kernel(const float* __restrict__ w0, const float* __restrict__ w1,
                                  const float* __restrict__ w2, const float* __restrict__ w3,
                                  const float* __restrict__ w4, const float* __restrict__ w5,
                                  float* __restrict__ wt) {
    int id = blockIdx.x * blockDim.x + threadIdx.x;
    if (id >= 6 * HID * HID) return;
    int w   = id >> 14;          // /16384
    int rem = id & 16383;
    int r   = rem >> 7;          // output-dim row of W
    int c   = rem & 127;         // input-dim col of W
    const float* src;
    switch (w) {
        case 0: src = w0; break; case 1: src = w1; break;
        case 2: src = w2; break; case 3: src = w3; break;
        case 4: src = w4; break; default: src = w5; break;
    }
    // wt[w][k=c][j=r] = W[r][c]
    wt[(size_t)w * 16384 + c * HID + r] = src[r * HID + c];
}

// ---------------- scatter-add: agg[dst] += h[src], one warp per edge ----------------
__global__ __launch_bounds__(256) void scatter_kernel(
    const float* __restrict__ h, const int* __restrict__ src, const int* __restrict__ dst,
    float* __restrict__ agg)
{
    int wid  = (blockIdx.x * blockDim.x + threadIdx.x) >> 5;
    int lane = threadIdx.x & 31;
    if (wid >= N_EDGES) return;
    int s = __ldg(&src[wid]);    // uniform per warp -> single request
    int d = __ldg(&dst[wid]);
    const float4 v = *reinterpret_cast<const float4*>(h + (size_t)s * HID + lane * 4);
    float* p = agg + (size_t)d * HID + lane * 4;
    asm volatile("red.global.add.v4.f32 [%0], {%1, %2, %3, %4};"
                 :: "l"(p), "f"(v.x), "f"(v.y), "f"(v.z), "f"(v.w) : "memory");
}

// ---------------- fused SAGE GEMM: C = relu?(A @ WlT + B @ WrT + bias) ----------------
// A,B: [N_NODES x 128] row-major. WTl,WTr: k-major [k][j]. 64x128 tile, 8x4 per thread.
__global__ __launch_bounds__(256) void gemm_sage_kernel(
    const float* __restrict__ A, const float* __restrict__ B,
    const float* __restrict__ WTl, const float* __restrict__ WTr,
    const float* __restrict__ bias, float* __restrict__ C, int do_relu)
{
    __shared__ float As[64][32];
    __shared__ float Ws[32][128];

    const int tid = threadIdx.x;
    const int cg  = tid & 31;    // col group -> cols cg*4 .. cg*4+3
    const int rg  = tid >> 5;    // row group -> rows rg*8 .. rg*8+7
    const int row0 = blockIdx.x * 64;

    float acc[8][4];
#pragma unroll
    for (int m = 0; m < 8; ++m)
#pragma unroll
        for (int n = 0; n < 4; ++n) acc[m][n] = 0.f;

#pragma unroll 1
    for (int phase = 0; phase < 2; ++phase) {
        const float* Ap = phase ? B : A;
        const float* Wp = phase ? WTr : WTl;
#pragma unroll 1
        for (int kt = 0; kt < 4; ++kt) {
            const int k0 = kt * 32;
            __syncthreads();
            // A tile: 64 rows x 32 cols = 512 float4, 2 per thread
#pragma unroll
            for (int t = 0; t < 2; ++t) {
                int i = tid + t * 256;
                int r = i >> 3;
                int q = i & 7;
                int grow = row0 + r;
                float4 v = make_float4(0.f, 0.f, 0.f, 0.f);
                if (grow < N_NODES)
                    v = *reinterpret_cast<const float4*>(Ap + (size_t)grow * HID + k0 + q * 4);
                *reinterpret_cast<float4*>(&As[r][q * 4]) = v;
            }
            // W tile: 32 k-rows x 128 j-cols = 1024 float4, 4 per thread (coalesced)
#pragma unroll
            for (int t = 0; t < 4; ++t) {
                int i = tid + t * 256;
                int k = i >> 5;
                int j = i & 31;
                *reinterpret_cast<float4*>(&Ws[k][j * 4]) =
                    *reinterpret_cast<const float4*>(Wp + (size_t)(k0 + k) * HID + j * 4);
            }
            __syncthreads();
#pragma unroll
            for (int k = 0; k < 32; ++k) {
                float4 wv = *reinterpret_cast<float4*>(&Ws[k][cg * 4]);
                float a[8];
#pragma unroll
                for (int m = 0; m < 8; ++m) a[m] = As[rg * 8 + m][k];
#pragma unroll
                for (int m = 0; m < 8; ++m) {
                    acc[m][0] += a[m] * wv.x;
                    acc[m][1] += a[m] * wv.y;
                    acc[m][2] += a[m] * wv.z;
                    acc[m][3] += a[m] * wv.w;
                }
            }
        }
    }

    const float4 bv = *reinterpret_cast<const float4*>(bias + cg * 4);
#pragma unroll
    for (int m = 0; m < 8; ++m) {
        int grow = row0 + rg * 8 + m;
        if (grow >= N_NODES) break;
        float4 o;
        o.x = acc[m][0] + bv.x;
        o.y = acc[m][1] + bv.y;
        o.z = acc[m][2] + bv.z;
        o.w = acc[m][3] + bv.w;
        if (do_relu) {
            o.x = fmaxf(o.x, 0.f); o.y = fmaxf(o.y, 0.f);
            o.z = fmaxf(o.z, 0.f); o.w = fmaxf(o.w, 0.f);
        }
        *reinterpret_cast<float4*>(C + (size_t)grow * HID + cg * 4) = o;
    }
}

// ---------------- graph pooling: pooled[batch[i]] += h[i], one warp per node ----------------
__global__ __launch_bounds__(256) void pool_kernel(
    const float* __restrict__ h, const int* __restrict__ batch, float* __restrict__ pooled)
{
    int wid  = (blockIdx.x * blockDim.x + threadIdx.x) >> 5;
    int lane = threadIdx.x & 31;
    if (wid >= N_NODES) return;
    int g = __ldg(&batch[wid]);
    const float4 v = *reinterpret_cast<const float4*>(h + (size_t)wid * HID + lane * 4);
    float* p = pooled + (size_t)g * HID + lane * 4;
    asm volatile("red.global.add.v4.f32 [%0], {%1, %2, %3, %4};"
                 :: "l"(p), "f"(v.x), "f"(v.y), "f"(v.z), "f"(v.w) : "memory");
}

// ---------------- output head: out[g][c] = pooled[g] . Wout[c] + bout[c] ----------------
__global__ void out_kernel(const float* __restrict__ pooled, const float* __restrict__ Wout,
                           const float* __restrict__ bout, float* __restrict__ out)
{
    int id = threadIdx.x;            // 640 threads: g*10 + c
    if (id >= NUM_G * 10) return;
    int g = id / 10, c = id % 10;
    float s = bout[c];
    const float* pr = pooled + g * HID;
    const float* wr = Wout + c * HID;
#pragma unroll 4
    for (int k = 0; k < HID; ++k) s += pr[k] * wr[k];
    out[id] = s;
}

// ---------------- launch ----------------
extern "C" void kernel_launch(void* const* d_in, const int* in_sizes, int n_in,
                              void* d_out, int out_size) {
    const float* x     = (const float*)d_in[0];
    const int*   ei    = (const int*)  d_in[1];
    const int*   batch = (const int*)  d_in[2];
    const float* W1l   = (const float*)d_in[3];
    const float* b1    = (const float*)d_in[4];
    const float* W1r   = (const float*)d_in[5];
    const float* W2l   = (const float*)d_in[6];
    const float* b2    = (const float*)d_in[7];
    const float* W2r   = (const float*)d_in[8];
    const float* W3l   = (const float*)d_in[9];
    const float* b3    = (const float*)d_in[10];
    const float* W3r   = (const float*)d_in[11];
    const float* Wout  = (const float*)d_in[12];
    const float* bout  = (const float*)d_in[13];
    float* out = (float*)d_out;

    const int* src = ei;
    const int* dst = ei + N_EDGES;

    float *bufA, *bufB, *agg, *wt, *pooled;
    cudaGetSymbolAddress((void**)&bufA,   g_bufA);
    cudaGetSymbolAddress((void**)&bufB,   g_bufB);
    cudaGetSymbolAddress((void**)&agg,    g_agg);
    cudaGetSymbolAddress((void**)&wt,     g_wt);
    cudaGetSymbolAddress((void**)&pooled, g_pool);

    const int AGG_F4     = (N_NODES * HID) / 4;          // 3.2M float4
    const int ZERO_BLKS  = (AGG_F4 + 255) / 256;
    const int SCAT_BLKS  = (N_EDGES * 32 + 255) / 256;   // one warp per edge
    const int GEMM_BLKS  = (N_NODES + 63) / 64;
    const int POOL_BLKS  = (N_NODES * 32 + 255) / 256;

    transpose6_kernel<<<(6 * 16384 + 255) / 256, 256>>>(W1l, W1r, W2l, W2r, W3l, W3r, wt);

    // Layer 1: x -> bufA (relu)
    zero_kernel<<<ZERO_BLKS, 256>>>(agg, AGG_F4);
    scatter_kernel<<<SCAT_BLKS, 256>>>(x, src, dst, agg);
    gemm_sage_kernel<<<GEMM_BLKS, 256>>>(agg, x, wt + 0 * 16384, wt + 1 * 16384, b1, bufA, 1);

    // Layer 2: bufA -> bufB (relu)
    zero_kernel<<<ZERO_BLKS, 256>>>(agg, AGG_F4);
    scatter_kernel<<<SCAT_BLKS, 256>>>(bufA, src, dst, agg);
    gemm_sage_kernel<<<GEMM_BLKS, 256>>>(agg, bufA, wt + 2 * 16384, wt + 3 * 16384, b2, bufB, 1);

    // Layer 3: bufB -> bufA (no relu)
    zero_kernel<<<ZERO_BLKS, 256>>>(agg, AGG_F4);
    scatter_kernel<<<SCAT_BLKS, 256>>>(bufB, src, dst, agg);
    gemm_sage_kernel<<<GEMM_BLKS, 256>>>(agg, bufB, wt + 4 * 16384, wt + 5 * 16384, b3, bufA, 0);

    // Pool + head
    zero_kernel<<<8, 256>>>(pooled, (NUM_G * HID) / 4);
    pool_kernel<<<POOL_BLKS, 256>>>(bufA, batch, pooled);
    out_kernel<<<1, 640>>>(pooled, Wout, bout, out);
}

// round 5
// speedup vs baseline: 1.2611x; 1.2611x over previous
#include <cuda_runtime.h>
#include <cstdint>

#define N_NODES   100000
#define N_EDGES   1600000
#define HID       128
#define NUM_G     64

// ---------------- scratch (static device globals; no allocation) ----------------
__device__ float g_bufA[(size_t)N_NODES * HID];
__device__ float g_bufB[(size_t)N_NODES * HID];
__device__ float g_agg [(size_t)N_NODES * HID];
__device__ float g_wt  [6 * HID * HID];        // transposed weights, k-major
__device__ float g_pool[NUM_G * HID];
__device__ int   g_deg   [N_NODES];
__device__ int   g_rowptr[N_NODES + 1];
__device__ int   g_cursor[N_NODES];
__device__ int   g_csrsrc[N_EDGES];

// ---------------- zero (float4) ----------------
__global__ void zero_kernel(float* __restrict__ p, int n4) {
    int i = blockIdx.x * blockDim.x + threadIdx.x;
    if (i < n4) reinterpret_cast<float4*>(p)[i] = make_float4(0.f, 0.f, 0.f, 0.f);
}

__global__ void zero_int_kernel(int* __restrict__ p, int n) {
    int i = blockIdx.x * blockDim.x + threadIdx.x;
    if (i < n) p[i] = 0;
}

// ---------------- CSR build ----------------
__global__ __launch_bounds__(256) void hist_kernel(const int* __restrict__ dst, int* __restrict__ deg) {
    int i = blockIdx.x * blockDim.x + threadIdx.x;
    if (i < N_EDGES) atomicAdd(&deg[dst[i]], 1);
}

// single-block exclusive scan of deg -> row_ptr (+cursor copy)
__global__ __launch_bounds__(1024) void scan_kernel(const int* __restrict__ deg,
                                                    int* __restrict__ row_ptr,
                                                    int* __restrict__ cursor) {
    const int T = 1024;
    int t = threadIdx.x;
    const int per = (N_NODES + T - 1) / T;      // 98
    int begin = t * per;
    int endi  = begin + per; if (endi > N_NODES) endi = N_NODES;
    int sum = 0;
    for (int i = begin; i < endi; ++i) sum += deg[i];
    __shared__ int partial[T];
    partial[t] = sum;
    __syncthreads();
    // inclusive Hillis-Steele scan
    for (int off = 1; off < T; off <<= 1) {
        int v = (t >= off) ? partial[t - off] : 0;
        __syncthreads();
        partial[t] += v;
        __syncthreads();
    }
    int run = (t == 0) ? 0 : partial[t - 1];   // exclusive offset for this chunk
    for (int i = begin; i < endi; ++i) {
        row_ptr[i] = run;
        cursor[i]  = run;
        run += deg[i];
    }
    if (t == T - 1) row_ptr[N_NODES] = partial[T - 1];
}

__global__ __launch_bounds__(256) void fill_kernel(const int* __restrict__ src,
                                                   const int* __restrict__ dst,
                                                   int* __restrict__ cursor,
                                                   int* __restrict__ csr_src) {
    int i = blockIdx.x * blockDim.x + threadIdx.x;
    if (i >= N_EDGES) return;
    int d = dst[i];
    int p = atomicAdd(&cursor[d], 1);
    csr_src[p] = src[i];
}

// ---------------- transpose 6 weight matrices [128x128] -> k-major ----------------
__global__ void transpose6_kernel(const float* __restrict__ w0, const float* __restrict__ w1,
                                  const float* __restrict__ w2, const float* __restrict__ w3,
                                  const float* __restrict__ w4, const float* __restrict__ w5,
                                  float* __restrict__ wt) {
    int id = blockIdx.x * blockDim.x + threadIdx.x;
    if (id >= 6 * HID * HID) return;
    int w   = id >> 14;
    int rem = id & 16383;
    int r   = rem >> 7;
    int c   = rem & 127;
    const float* src;
    switch (w) {
        case 0: src = w0; break; case 1: src = w1; break;
        case 2: src = w2; break; case 3: src = w3; break;
        case 4: src = w4; break; default: src = w5; break;
    }
    wt[(size_t)w * 16384 + c * HID + r] = src[r * HID + c];
}

// ---------------- gather aggregation: agg[n] = sum over incoming edges h[src] ----------------
// One warp per node; 4 floats per lane held in registers; no atomics, no zeroing.
__global__ __launch_bounds__(256) void gather_kernel(
    const float* __restrict__ h, const int* __restrict__ row_ptr,
    const int* __restrict__ csr_src, float* __restrict__ agg)
{
    int node = (blockIdx.x * blockDim.x + threadIdx.x) >> 5;
    int lane = threadIdx.x & 31;
    if (node >= N_NODES) return;
    int e   = __ldg(&row_ptr[node]);
    int end = __ldg(&row_ptr[node + 1]);
    float4 acc = make_float4(0.f, 0.f, 0.f, 0.f);

    // unroll-by-2 to expose MLP on the gathered rows
    for (; e + 1 < end; e += 2) {
        int s0 = __ldg(&csr_src[e]);
        int s1 = __ldg(&csr_src[e + 1]);
        float4 v0 = *reinterpret_cast<const float4*>(h + (size_t)s0 * HID + lane * 4);
        float4 v1 = *reinterpret_cast<const float4*>(h + (size_t)s1 * HID + lane * 4);
        acc.x += v0.x; acc.y += v0.y; acc.z += v0.z; acc.w += v0.w;
        acc.x += v1.x; acc.y += v1.y; acc.z += v1.z; acc.w += v1.w;
    }
    if (e < end) {
        int s0 = __ldg(&csr_src[e]);
        float4 v0 = *reinterpret_cast<const float4*>(h + (size_t)s0 * HID + lane * 4);
        acc.x += v0.x; acc.y += v0.y; acc.z += v0.z; acc.w += v0.w;
    }
    *reinterpret_cast<float4*>(agg + (size_t)node * HID + lane * 4) = acc;
}

// ---------------- fused SAGE GEMM: C = relu?(A @ WlT + B @ WrT + bias) ----------------
__global__ __launch_bounds__(256) void gemm_sage_kernel(
    const float* __restrict__ A, const float* __restrict__ B,
    const float* __restrict__ WTl, const float* __restrict__ WTr,
    const float* __restrict__ bias, float* __restrict__ C, int do_relu)
{
    __shared__ float As[64][32];
    __shared__ float Ws[32][128];

    const int tid = threadIdx.x;
    const int cg  = tid & 31;
    const int rg  = tid >> 5;
    const int row0 = blockIdx.x * 64;

    float acc[8][4];
#pragma unroll
    for (int m = 0; m < 8; ++m)
#pragma unroll
        for (int n = 0; n < 4; ++n) acc[m][n] = 0.f;

#pragma unroll 1
    for (int phase = 0; phase < 2; ++phase) {
        const float* Ap = phase ? B : A;
        const float* Wp = phase ? WTr : WTl;
#pragma unroll 1
        for (int kt = 0; kt < 4; ++kt) {
            const int k0 = kt * 32;
            __syncthreads();
#pragma unroll
            for (int t = 0; t < 2; ++t) {
                int i = tid + t * 256;
                int r = i >> 3;
                int q = i & 7;
                int grow = row0 + r;
                float4 v = make_float4(0.f, 0.f, 0.f, 0.f);
                if (grow < N_NODES)
                    v = *reinterpret_cast<const float4*>(Ap + (size_t)grow * HID + k0 + q * 4);
                *reinterpret_cast<float4*>(&As[r][q * 4]) = v;
            }
#pragma unroll
            for (int t = 0; t < 4; ++t) {
                int i = tid + t * 256;
                int k = i >> 5;
                int j = i & 31;
                *reinterpret_cast<float4*>(&Ws[k][j * 4]) =
                    *reinterpret_cast<const float4*>(Wp + (size_t)(k0 + k) * HID + j * 4);
            }
            __syncthreads();
#pragma unroll
            for (int k = 0; k < 32; ++k) {
                float4 wv = *reinterpret_cast<float4*>(&Ws[k][cg * 4]);
                float a[8];
#pragma unroll
                for (int m = 0; m < 8; ++m) a[m] = As[rg * 8 + m][k];
#pragma unroll
                for (int m = 0; m < 8; ++m) {
                    acc[m][0] += a[m] * wv.x;
                    acc[m][1] += a[m] * wv.y;
                    acc[m][2] += a[m] * wv.z;
                    acc[m][3] += a[m] * wv.w;
                }
            }
        }
    }

    const float4 bv = *reinterpret_cast<const float4*>(bias + cg * 4);
#pragma unroll
    for (int m = 0; m < 8; ++m) {
        int grow = row0 + rg * 8 + m;
        if (grow >= N_NODES) break;
        float4 o;
        o.x = acc[m][0] + bv.x;
        o.y = acc[m][1] + bv.y;
        o.z = acc[m][2] + bv.z;
        o.w = acc[m][3] + bv.w;
        if (do_relu) {
            o.x = fmaxf(o.x, 0.f); o.y = fmaxf(o.y, 0.f);
            o.z = fmaxf(o.z, 0.f); o.w = fmaxf(o.w, 0.f);
        }
        *reinterpret_cast<float4*>(C + (size_t)grow * HID + cg * 4) = o;
    }
}

// ---------------- graph pooling: pooled[batch[i]] += h[i], one warp per node ----------------
__global__ __launch_bounds__(256) void pool_kernel(
    const float* __restrict__ h, const int* __restrict__ batch, float* __restrict__ pooled)
{
    int wid  = (blockIdx.x * blockDim.x + threadIdx.x) >> 5;
    int lane = threadIdx.x & 31;
    if (wid >= N_NODES) return;
    int g = __ldg(&batch[wid]);
    const float4 v = *reinterpret_cast<const float4*>(h + (size_t)wid * HID + lane * 4);
    float* p = pooled + (size_t)g * HID + lane * 4;
    asm volatile("red.global.add.v4.f32 [%0], {%1, %2, %3, %4};"
                 :: "l"(p), "f"(v.x), "f"(v.y), "f"(v.z), "f"(v.w) : "memory");
}

// ---------------- output head ----------------
__global__ void out_kernel(const float* __restrict__ pooled, const float* __restrict__ Wout,
                           const float* __restrict__ bout, float* __restrict__ out)
{
    int id = threadIdx.x;
    if (id >= NUM_G * 10) return;
    int g = id / 10, c = id % 10;
    float s = bout[c];
    const float* pr = pooled + g * HID;
    const float* wr = Wout + c * HID;
#pragma unroll 4
    for (int k = 0; k < HID; ++k) s += pr[k] * wr[k];
    out[id] = s;
}

// ---------------- launch ----------------
extern "C" void kernel_launch(void* const* d_in, const int* in_sizes, int n_in,
                              void* d_out, int out_size) {
    const float* x     = (const float*)d_in[0];
    const int*   ei    = (const int*)  d_in[1];
    const int*   batch = (const int*)  d_in[2];
    const float* W1l   = (const float*)d_in[3];
    const float* b1    = (const float*)d_in[4];
    const float* W1r   = (const float*)d_in[5];
    const float* W2l   = (const float*)d_in[6];
    const float* b2    = (const float*)d_in[7];
    const float* W2r   = (const float*)d_in[8];
    const float* W3l   = (const float*)d_in[9];
    const float* b3    = (const float*)d_in[10];
    const float* W3r   = (const float*)d_in[11];
    const float* Wout  = (const float*)d_in[12];
    const float* bout  = (const float*)d_in[13];
    float* out = (float*)d_out;

    const int* src = ei;
    const int* dst = ei + N_EDGES;

    float *bufA, *bufB, *agg, *wt, *pooled;
    int *deg, *rowptr, *cursor, *csrsrc;
    cudaGetSymbolAddress((void**)&bufA,   g_bufA);
    cudaGetSymbolAddress((void**)&bufB,   g_bufB);
    cudaGetSymbolAddress((void**)&agg,    g_agg);
    cudaGetSymbolAddress((void**)&wt,     g_wt);
    cudaGetSymbolAddress((void**)&pooled, g_pool);
    cudaGetSymbolAddress((void**)&deg,    g_deg);
    cudaGetSymbolAddress((void**)&rowptr, g_rowptr);
    cudaGetSymbolAddress((void**)&cursor, g_cursor);
    cudaGetSymbolAddress((void**)&csrsrc, g_csrsrc);

    const int EDGE_BLKS  = (N_EDGES + 255) / 256;
    const int GATH_BLKS  = (N_NODES * 32 + 255) / 256;   // one warp per node
    const int GEMM_BLKS  = (N_NODES + 63) / 64;
    const int POOL_BLKS  = (N_NODES * 32 + 255) / 256;

    // --- CSR build (once per launch) ---
    zero_int_kernel<<<(N_NODES + 255) / 256, 256>>>(deg, N_NODES);
    hist_kernel<<<EDGE_BLKS, 256>>>(dst, deg);
    scan_kernel<<<1, 1024>>>(deg, rowptr, cursor);
    fill_kernel<<<EDGE_BLKS, 256>>>(src, dst, cursor, csrsrc);

    transpose6_kernel<<<(6 * 16384 + 255) / 256, 256>>>(W1l, W1r, W2l, W2r, W3l, W3r, wt);

    // Layer 1: x -> bufA (relu)
    gather_kernel<<<GATH_BLKS, 256>>>(x, rowptr, csrsrc, agg);
    gemm_sage_kernel<<<GEMM_BLKS, 256>>>(agg, x, wt + 0 * 16384, wt + 1 * 16384, b1, bufA, 1);

    // Layer 2: bufA -> bufB (relu)
    gather_kernel<<<GATH_BLKS, 256>>>(bufA, rowptr, csrsrc, agg);
    gemm_sage_kernel<<<GEMM_BLKS, 256>>>(agg, bufA, wt + 2 * 16384, wt + 3 * 16384, b2, bufB, 1);

    // Layer 3: bufB -> bufA (no relu)
    gather_kernel<<<GATH_BLKS, 256>>>(bufB, rowptr, csrsrc, agg);
    gemm_sage_kernel<<<GEMM_BLKS, 256>>>(agg, bufB, wt + 4 * 16384, wt + 5 * 16384, b3, bufA, 0);

    // Pool + head
    zero_kernel<<<8, 256>>>(pooled, (NUM_G * HID) / 4);
    pool_kernel<<<POOL_BLKS, 256>>>(bufA, batch, pooled);
    out_kernel<<<1, 640>>>(pooled, Wout, bout, out);
}

// round 9
// speedup vs baseline: 1.2931x; 1.0254x over previous
#include <cuda_runtime.h>
#include <cstdint>

#define N_NODES   100000
#define N_EDGES   1600000
#define HID       128
#define NUM_G     64

// ---------------- scratch (static device globals; no allocation) ----------------
__device__ float g_bufA[(size_t)N_NODES * HID];
__device__ float g_bufB[(size_t)N_NODES * HID];
__device__ float g_wt  [6 * HID * HID];        // transposed weights, k-major
__device__ float g_pool[NUM_G * HID];
__device__ int   g_deg   [N_NODES];
__device__ int   g_rowptr[N_NODES + 1];
__device__ int   g_cursor[N_NODES];
__device__ int   g_csrsrc[N_EDGES];

// ---------------- zero helpers ----------------
__global__ void zero_kernel(float* __restrict__ p, int n4) {
    int i = blockIdx.x * blockDim.x + threadIdx.x;
    if (i < n4) reinterpret_cast<float4*>(p)[i] = make_float4(0.f, 0.f, 0.f, 0.f);
}
__global__ void zero_int_kernel(int* __restrict__ p, int n) {
    int i = blockIdx.x * blockDim.x + threadIdx.x;
    if (i < n) p[i] = 0;
}

// ---------------- CSR build ----------------
__global__ __launch_bounds__(256) void hist_kernel(const int* __restrict__ dst, int* __restrict__ deg) {
    int i = blockIdx.x * blockDim.x + threadIdx.x;
    if (i < N_EDGES) atomicAdd(&deg[dst[i]], 1);
}

__global__ __launch_bounds__(1024) void scan_kernel(const int* __restrict__ deg,
                                                    int* __restrict__ row_ptr,
                                                    int* __restrict__ cursor) {
    const int T = 1024;
    int t = threadIdx.x;
    const int per = (N_NODES + T - 1) / T;
    int begin = t * per;
    int endi  = begin + per; if (endi > N_NODES) endi = N_NODES;
    int sum = 0;
    for (int i = begin; i < endi; ++i) sum += deg[i];
    __shared__ int partial[T];
    partial[t] = sum;
    __syncthreads();
    for (int off = 1; off < T; off <<= 1) {
        int v = (t >= off) ? partial[t - off] : 0;
        __syncthreads();
        partial[t] += v;
        __syncthreads();
    }
    int run = (t == 0) ? 0 : partial[t - 1];
    for (int i = begin; i < endi; ++i) {
        row_ptr[i] = run;
        cursor[i]  = run;
        run += deg[i];
    }
    if (t == T - 1) row_ptr[N_NODES] = partial[T - 1];
}

__global__ __launch_bounds__(256) void fill_kernel(const int* __restrict__ src,
                                                   const int* __restrict__ dst,
                                                   int* __restrict__ cursor,
                                                   int* __restrict__ csr_src) {
    int i = blockIdx.x * blockDim.x + threadIdx.x;
    if (i >= N_EDGES) return;
    int d = dst[i];
    int p = atomicAdd(&cursor[d], 1);
    csr_src[p] = src[i];
}

// ---------------- transpose 6 weight matrices [128x128] -> k-major ----------------
__global__ void transpose6_kernel(const float* __restrict__ w0, const float* __restrict__ w1,
                                  const float* __restrict__ w2, const float* __restrict__ w3,
                                  const float* __restrict__ w4, const float* __restrict__ w5,
                                  float* __restrict__ wt) {
    int id = blockIdx.x * blockDim.x + threadIdx.x;
    if (id >= 6 * HID * HID) return;
    int w   = id >> 14;
    int rem = id & 16383;
    int r   = rem >> 7;
    int c   = rem & 127;
    const float* src;
    switch (w) {
        case 0: src = w0; break; case 1: src = w1; break;
        case 2: src = w2; break; case 3: src = w3; break;
        case 4: src = w4; break; default: src = w5; break;
    }
    wt[(size_t)w * 16384 + c * HID + r] = src[r * HID + c];
}

// ---------------- fused SAGE layer ----------------
// Per 64-row block:
//   phase G: gather agg rows (CSR) into SMEM Ag[64][128]  (one warp per node)
//   phase 0: acc += Ag @ WlT          (A operand from SMEM)
//   phase 1: acc += h-rows @ WrT      (staged through first 8KB of Ag)
//   epilogue: mode 0 -> C = relu(acc+bias); mode 1 -> red.add into pooled[batch[row]]
__global__ __launch_bounds__(256) void sage_fused_kernel(
    const float* __restrict__ h, const int* __restrict__ row_ptr,
    const int* __restrict__ csr_src,
    const float* __restrict__ WTl, const float* __restrict__ WTr,
    const float* __restrict__ bias, float* __restrict__ C,
    const int* __restrict__ batch, float* __restrict__ pooled, int mode)
{
    __shared__ float Ag[64][128];   // 32KB; first 8KB reused as Hs[64][32] in phase 1
    __shared__ float Ws[32][128];   // 16KB

    const int tid  = threadIdx.x;
    const int lane = tid & 31;
    const int warp = tid >> 5;
    const int cg   = tid & 31;      // output cols cg*4..cg*4+3
    const int rg   = tid >> 5;      // output rows rg*8..rg*8+7
    const int row0 = blockIdx.x * 64;

    // ---- phase G: gather ----
    for (int nb = warp; nb < 64; nb += 8) {
        int node = row0 + nb;
        float4 acc = make_float4(0.f, 0.f, 0.f, 0.f);
        if (node < N_NODES) {
            int e   = __ldg(&row_ptr[node]);
            int end = __ldg(&row_ptr[node + 1]);
            for (; e + 1 < end; e += 2) {
                int s0 = __ldg(&csr_src[e]);
                int s1 = __ldg(&csr_src[e + 1]);
                float4 v0 = *reinterpret_cast<const float4*>(h + (size_t)s0 * HID + lane * 4);
                float4 v1 = *reinterpret_cast<const float4*>(h + (size_t)s1 * HID + lane * 4);
                acc.x += v0.x + v1.x; acc.y += v0.y + v1.y;
                acc.z += v0.z + v1.z; acc.w += v0.w + v1.w;
            }
            if (e < end) {
                int s0 = __ldg(&csr_src[e]);
                float4 v0 = *reinterpret_cast<const float4*>(h + (size_t)s0 * HID + lane * 4);
                acc.x += v0.x; acc.y += v0.y; acc.z += v0.z; acc.w += v0.w;
            }
        }
        *reinterpret_cast<float4*>(&Ag[nb][lane * 4]) = acc;
    }
    __syncthreads();

    float acc[8][4];
#pragma unroll
    for (int m = 0; m < 8; ++m)
#pragma unroll
        for (int n = 0; n < 4; ++n) acc[m][n] = 0.f;

    // ---- phase 0: acc += Ag @ WlT (A from SMEM Ag) ----
#pragma unroll 1
    for (int kt = 0; kt < 4; ++kt) {
        const int k0 = kt * 32;
#pragma unroll
        for (int t = 0; t < 4; ++t) {
            int i = tid + t * 256;
            int k = i >> 5;
            int j = i & 31;
            *reinterpret_cast<float4*>(&Ws[k][j * 4]) =
                *reinterpret_cast<const float4*>(WTl + (size_t)(k0 + k) * HID + j * 4);
        }
        __syncthreads();
#pragma unroll
        for (int k = 0; k < 32; ++k) {
            float4 wv = *reinterpret_cast<float4*>(&Ws[k][cg * 4]);
            float a[8];
#pragma unroll
            for (int m = 0; m < 8; ++m) a[m] = Ag[rg * 8 + m][k0 + k];
#pragma unroll
            for (int m = 0; m < 8; ++m) {
                acc[m][0] += a[m] * wv.x;
                acc[m][1] += a[m] * wv.y;
                acc[m][2] += a[m] * wv.z;
                acc[m][3] += a[m] * wv.w;
            }
        }
        __syncthreads();
    }

    // ---- phase 1: acc += h @ WrT (stage h tile into Hs = front of Ag) ----
    float (*Hs)[32] = reinterpret_cast<float(*)[32]>(&Ag[0][0]);
#pragma unroll 1
    for (int kt = 0; kt < 4; ++kt) {
        const int k0 = kt * 32;
#pragma unroll
        for (int t = 0; t < 2; ++t) {
            int i = tid + t * 256;
            int r = i >> 3;
            int q = i & 7;
            int grow = row0 + r;
            float4 v = make_float4(0.f, 0.f, 0.f, 0.f);
            if (grow < N_NODES)
                v = *reinterpret_cast<const float4*>(h + (size_t)grow * HID + k0 + q * 4);
            *reinterpret_cast<float4*>(&Hs[r][q * 4]) = v;
        }
#pragma unroll
        for (int t = 0; t < 4; ++t) {
            int i = tid + t * 256;
            int k = i >> 5;
            int j = i & 31;
            *reinterpret_cast<float4*>(&Ws[k][j * 4]) =
                *reinterpret_cast<const float4*>(WTr + (size_t)(k0 + k) * HID + j * 4);
        }
        __syncthreads();
#pragma unroll
        for (int k = 0; k < 32; ++k) {
            float4 wv = *reinterpret_cast<float4*>(&Ws[k][cg * 4]);
            float a[8];
#pragma unroll
            for (int m = 0; m < 8; ++m) a[m] = Hs[rg * 8 + m][k];
#pragma unroll
            for (int m = 0; m < 8; ++m) {
                acc[m][0] += a[m] * wv.x;
                acc[m][1] += a[m] * wv.y;
                acc[m][2] += a[m] * wv.z;
                acc[m][3] += a[m] * wv.w;
            }
        }
        __syncthreads();
    }

    // ---- epilogue ----
    const float4 bv = *reinterpret_cast<const float4*>(bias + cg * 4);
    if (mode == 0) {                     // write C with relu
#pragma unroll
        for (int m = 0; m < 8; ++m) {
            int grow = row0 + rg * 8 + m;
            if (grow >= N_NODES) break;
            float4 o;
            o.x = fmaxf(acc[m][0] + bv.x, 0.f);
            o.y = fmaxf(acc[m][1] + bv.y, 0.f);
            o.z = fmaxf(acc[m][2] + bv.z, 0.f);
            o.w = fmaxf(acc[m][3] + bv.w, 0.f);
            *reinterpret_cast<float4*>(C + (size_t)grow * HID + cg * 4) = o;
        }
    } else {                             // pool: no relu, reduce into pooled
#pragma unroll
        for (int m = 0; m < 8; ++m) {
            int grow = row0 + rg * 8 + m;
            if (grow >= N_NODES) break;
            float ox = acc[m][0] + bv.x;
            float oy = acc[m][1] + bv.y;
            float oz = acc[m][2] + bv.z;
            float ow = acc[m][3] + bv.w;
            int g = __ldg(&batch[grow]);
            float* p = pooled + (size_t)g * HID + cg * 4;
            asm volatile("red.global.add.v4.f32 [%0], {%1, %2, %3, %4};"
                         :: "l"(p), "f"(ox), "f"(oy), "f"(oz), "f"(ow) : "memory");
        }
    }
}

// ---------------- output head ----------------
__global__ void out_kernel(const float* __restrict__ pooled, const float* __restrict__ Wout,
                           const float* __restrict__ bout, float* __restrict__ out)
{
    int id = threadIdx.x;
    if (id >= NUM_G * 10) return;
    int g = id / 10, c = id % 10;
    float s = bout[c];
    const float* pr = pooled + g * HID;
    const float* wr = Wout + c * HID;
#pragma unroll 4
    for (int k = 0; k < HID; ++k) s += pr[k] * wr[k];
    out[id] = s;
}

// ---------------- launch ----------------
extern "C" void kernel_launch(void* const* d_in, const int* in_sizes, int n_in,
                              void* d_out, int out_size) {
    const float* x     = (const float*)d_in[0];
    const int*   ei    = (const int*)  d_in[1];
    const int*   batch = (const int*)  d_in[2];
    const float* W1l   = (const float*)d_in[3];
    const float* b1    = (const float*)d_in[4];
    const float* W1r   = (const float*)d_in[5];
    const float* W2l   = (const float*)d_in[6];
    const float* b2    = (const float*)d_in[7];
    const float* W2r   = (const float*)d_in[8];
    const float* W3l   = (const float*)d_in[9];
    const float* b3    = (const float*)d_in[10];
    const float* W3r   = (const float*)d_in[11];
    const float* Wout  = (const float*)d_in[12];
    const float* bout  = (const float*)d_in[13];
    float* out = (float*)d_out;

    const int* src = ei;
    const int* dst = ei + N_EDGES;

    float *bufA, *bufB, *wt, *pooled;
    int *deg, *rowptr, *cursor, *csrsrc;
    cudaGetSymbolAddress((void**)&bufA,   g_bufA);
    cudaGetSymbolAddress((void**)&bufB,   g_bufB);
    cudaGetSymbolAddress((void**)&wt,     g_wt);
    cudaGetSymbolAddress((void**)&pooled, g_pool);
    cudaGetSymbolAddress((void**)&deg,    g_deg);
    cudaGetSymbolAddress((void**)&rowptr, g_rowptr);
    cudaGetSymbolAddress((void**)&cursor, g_cursor);
    cudaGetSymbolAddress((void**)&csrsrc, g_csrsrc);

    const int EDGE_BLKS = (N_EDGES + 255) / 256;
    const int GEMM_BLKS = (N_NODES + 63) / 64;

    // --- CSR build (once per launch) ---
    zero_int_kernel<<<(N_NODES + 255) / 256, 256>>>(deg, N_NODES);
    hist_kernel<<<EDGE_BLKS, 256>>>(dst, deg);
    scan_kernel<<<1, 1024>>>(deg, rowptr, cursor);
    fill_kernel<<<EDGE_BLKS, 256>>>(src, dst, cursor, csrsrc);

    transpose6_kernel<<<(6 * 16384 + 255) / 256, 256>>>(W1l, W1r, W2l, W2r, W3l, W3r, wt);
    zero_kernel<<<8, 256>>>(pooled, (NUM_G * HID) / 4);

    // Layer 1: x -> bufA (relu)
    sage_fused_kernel<<<GEMM_BLKS, 256>>>(x, rowptr, csrsrc,
        wt + 0 * 16384, wt + 1 * 16384, b1, bufA, batch, pooled, 0);

    // Layer 2: bufA -> bufB (relu)
    sage_fused_kernel<<<GEMM_BLKS, 256>>>(bufA, rowptr, csrsrc,
        wt + 2 * 16384, wt + 3 * 16384, b2, bufB, batch, pooled, 0);

    // Layer 3: bufB -> pooled (no relu, fused pooling; no C write)
    sage_fused_kernel<<<GEMM_BLKS, 256>>>(bufB, rowptr, csrsrc,
        wt + 4 * 16384, wt + 5 * 16384, b3, bufA, batch, pooled, 1);

    // Head
    out_kernel<<<1, 640>>>(pooled, Wout, bout, out);
}